// round 8
// baseline (speedup 1.0000x reference)
#include <cuda_runtime.h>
#include <cstdint>

typedef unsigned long long ull;

#define NB 512
#define NT 512
#define NC 64
#define PAIRS 4            // batches per CTA (one A/B warp pair each)
#define THREADS 256        // 8 warps: wid 0-3 = role A, wid 4-7 = role B
#define FULLMASK 0xffffffffu

__device__ float    g_partial[NB];
__device__ unsigned g_done;   // self-resetting completion counter

static __device__ __forceinline__ ull fma2(ull a, ull b, ull c) {
    ull d; asm("fma.rn.f32x2 %0,%1,%2,%3;" : "=l"(d) : "l"(a), "l"(b), "l"(c)); return d;
}
static __device__ __forceinline__ ull add2(ull a, ull b) {
    ull d; asm("add.rn.f32x2 %0,%1,%2;" : "=l"(d) : "l"(a), "l"(b)); return d;
}
static __device__ __forceinline__ ull pack2(float x, float y) {
    ull d; asm("mov.b64 %0,{%1,%2};" : "=l"(d) : "f"(x), "f"(y)); return d;
}
static __device__ __forceinline__ void unpack2(ull v, float& x, float& y) {
    asm("mov.b64 {%0,%1},%2;" : "=f"(x), "=f"(y) : "l"(v));
}

// Split named barriers (64 threads = one A/B warp pair).
#define BAR_SYNC(id)   asm volatile("bar.sync %0, 64;"   :: "r"(id) : "memory")
#define BAR_ARRIVE(id) asm volatile("bar.arrive %0, 64;" :: "r"(id) : "memory")

// Role A step: rows 0..31 partial, combine with B's partial, epilogue, store p.
#define STEP_A(EMC, MBIT, REN) do {                                              \
    float ex_ = __expf((EMC).x), ey_ = __expf((EMC).y);                          \
    const ulonglong2* pb_ = (const ulonglong2*)pbuf[pair];                       \
    ull qa0_=0, qa1_=0, qa2_=0, qa3_=0;                                          \
    _Pragma("unroll")                                                            \
    for (int g_ = 0; g_ < 16; g_++) {                                            \
        ulonglong2 v_ = pb_[g_];                                                 \
        if (g_ & 1) { qa2_=fma2(v_.x,e2[2*g_],qa2_); qa3_=fma2(v_.y,e2[2*g_+1],qa3_); } \
        else        { qa0_=fma2(v_.x,e2[2*g_],qa0_); qa1_=fma2(v_.y,e2[2*g_+1],qa1_); } \
    }                                                                            \
    ull qq_ = add2(add2(qa0_, qa1_), add2(qa2_, qa3_));                          \
    BAR_SYNC(idA);                       /* B's partial is ready */              \
    qq_ = add2(qq_, part[pair][lane]);                                           \
    float qx_, qy_; unpack2(qq_, qx_, qy_);                                      \
    if (MBIT) { px = qx_ * ex_; py = qy_ * ey_; }                                \
    if (REN) {                                                                   \
        /* p strictly positive & normal -> int-bit max valid; exact 2^k scale */ \
        int mb_ = __reduce_max_sync(FULLMASK, __float_as_int(fmaxf(px, py)));    \
        int e_  = mb_ >> 23;                                                     \
        float inv_ = __int_as_float((254 - e_) << 23);                           \
        px *= inv_; py *= inv_;                                                  \
        logZ += (float)(e_ - 127) * 0.6931471805599453f;                         \
    }                                                                            \
    ((float4*)pbuf[pair])[lane] = make_float4(px, px, py, py);                   \
    __syncwarp();                                                                \
    BAR_ARRIVE(idB);                     /* p_t published */                     \
} while (0)

// Role B step: wait for p, rows 32..63 partial, publish.
#define STEP_B() do {                                                            \
    BAR_SYNC(idB);                       /* p_{t-1} is ready */                  \
    const ulonglong2* pb_ = ((const ulonglong2*)pbuf[pair]) + 16;                \
    ull qa0_=0, qa1_=0, qa2_=0, qa3_=0;                                          \
    _Pragma("unroll")                                                            \
    for (int g_ = 0; g_ < 16; g_++) {                                            \
        ulonglong2 v_ = pb_[g_];                                                 \
        if (g_ & 1) { qa2_=fma2(v_.x,e2[2*g_],qa2_); qa3_=fma2(v_.y,e2[2*g_+1],qa3_); } \
        else        { qa0_=fma2(v_.x,e2[2*g_],qa0_); qa1_=fma2(v_.y,e2[2*g_+1],qa1_); } \
    }                                                                            \
    part[pair][lane] = add2(add2(qa0_, qa1_), add2(qa2_, qa3_));                 \
    BAR_ARRIVE(idA);                     /* partial published */                 \
} while (0)

__global__ void __launch_bounds__(THREADS, 1) crf_forward(
    const float* __restrict__ emissions,   // [B, T, C]
    const int*   __restrict__ tags,        // [B, T]
    const int*   __restrict__ mask,        // [B, T]
    const float* __restrict__ trans,       // [C, C]
    const float* __restrict__ startt,      // [C]
    const float* __restrict__ endt,        // [C]
    float*       __restrict__ out)         // [1]
{
    // p per pair, duplicated pairs: entry i = (p[i], p[i]) so broadcast LDS.128
    // feeds fma.rn.f32x2 (2 rows / load). Single-buffered: barrier protocol
    // guarantees no WAR (A writes p_t only after B arrived post-read of p_{t-1}).
    __shared__ __align__(16) ull   pbuf[PAIRS][NC];
    __shared__ __align__(16) ull   part[PAIRS][32];   // B's partial q
    __shared__ float s_num[PAIRS];
    __shared__ bool  s_last;

    const int wid   = threadIdx.x >> 5;
    const int lane  = threadIdx.x & 31;
    const int pair  = wid & 3;
    const bool roleA = (wid < 4);
    const int b     = blockIdx.x * PAIRS + pair;
    const int j0    = lane * 2;
    const int idA   = 1 + pair;   // B -> A: partial ready
    const int idB   = 5 + pair;   // A -> B: p ready

    const float* em = emissions + (size_t)b * NT * NC;

    // ---- E = exp(transitions), this role's 32 rows, lane's two columns ----
    const int rbase = roleA ? 0 : 32;
    ull e2[32];
#pragma unroll
    for (int i = 0; i < 32; i++) {
        float2 tv = *(const float2*)(trans + (rbase + i) * NC + j0);
        e2[i] = pack2(__expf(tv.x), __expf(tv.y));
    }

    if (!roleA) {
        // ================= role B =================
        // Numerator here: overlaps role A's init.
        const int* tg = tags + (size_t)b * NT;
        const int* mk = mask + (size_t)b * NT;
        float num = 0.f;
        int   cnt = 0;
#pragma unroll 4
        for (int t = lane; t < NT; t += 32) {
            int tt = tg[t];
            int m  = mk[t];
            cnt += m;
            if (t > 0 && m)
                num += trans[tg[t - 1] * NC + tt] + em[(size_t)t * NC + tt];
        }
        cnt = __reduce_add_sync(FULLMASK, cnt);
#pragma unroll
        for (int o = 16; o > 0; o >>= 1)
            num += __shfl_down_sync(FULLMASK, num, o);
        if (lane == 0) {
            int t0 = tg[0];
            s_num[pair] = num + startt[t0] + em[t0] + endt[tg[cnt - 1]];
        }
        // Hot loop: 511 lean steps. (Ordering of s_num to A's final read is
        // carried by the 511 barrier phases in between.)
#pragma unroll 4
        for (int t = 1; t < NT; t++)
            STEP_B();
        BAR_SYNC(idB);   // consume A's final arrive (phase balance)
    } else {
        // ================= role A =================
        // Startup long-latency loads first.
        float2 em0  = *(const float2*)(em + j0);
        float2 emP0 = *(const float2*)(em + (size_t)1 * NC + j0);
        float2 emP1 = *(const float2*)(em + (size_t)2 * NC + j0);
        float2 emP2 = *(const float2*)(em + (size_t)3 * NC + j0);
        const int* mk = mask + (size_t)b * NT;
        int4   mk03 = *(const int4*)(mk);
        int4   mc   = *(const int4*)(mk + 4);
        float2 emc0 = *(const float2*)(em + (size_t)4 * NC + j0);
        float2 emc1 = *(const float2*)(em + (size_t)5 * NC + j0);
        float2 emc2 = *(const float2*)(em + (size_t)6 * NC + j0);
        float2 emc3 = *(const float2*)(em + (size_t)7 * NC + j0);
        float2 st2  = *(const float2*)(startt + j0);
        float2 et2  = *(const float2*)(endt + j0);

        // init t = 0 (values may be negative -> shfl fmax tree)
        float ax = st2.x + em0.x, ay = st2.y + em0.y;
        float m0 = fmaxf(ax, ay);
#pragma unroll
        for (int o = 16; o > 0; o >>= 1)
            m0 = fmaxf(m0, __shfl_xor_sync(FULLMASK, m0, o));
        float logZ = m0;
        float px = __expf(ax - m0);
        float py = __expf(ay - m0);
        ((float4*)pbuf[pair])[lane] = make_float4(px, px, py, py);
        __syncwarp();
        BAR_ARRIVE(idB);   // p_0 published

        // prologue t = 1..3 (renorm on the last)
        STEP_A(emP0, mk03.y, false);
        STEP_A(emP1, mk03.z, false);
        STEP_A(emP2, mk03.w, true);

        // main loop: groups of 4, next group's emissions/mask prefetched
#pragma unroll 1
        for (int t0 = 4; t0 < NT; t0 += 4) {
            float2 en0 = emc0, en1 = emc1, en2 = emc2, en3 = emc3;
            int4   mn  = mc;
            if (t0 + 4 < NT) {
                const float* p4 = em + (size_t)(t0 + 4) * NC + j0;
                en0 = *(const float2*)(p4);
                en1 = *(const float2*)(p4 + NC);
                en2 = *(const float2*)(p4 + 2 * NC);
                en3 = *(const float2*)(p4 + 3 * NC);
                mn  = *(const int4*)(mk + t0 + 4);
            }
            STEP_A(emc0, mc.x, false);
            STEP_A(emc1, mc.y, false);
            STEP_A(emc2, mc.z, false);
            STEP_A(emc3, mc.w, true);
            emc0 = en0; emc1 = en1; emc2 = en2; emc3 = en3; mc = mn;
        }

        // log denominator & per-batch loss (px/py = p_511 in registers)
        float contrib = px * __expf(et2.x) + py * __expf(et2.y);
#pragma unroll
        for (int o = 16; o > 0; o >>= 1)
            contrib += __shfl_down_sync(FULLMASK, contrib, o);
        if (lane == 0)
            g_partial[b] = logZ + __logf(contrib) - s_num[pair];
    }

    // ---- fused final reduction: last CTA to finish reduces all 512 ----
    __syncthreads();
    if (threadIdx.x == 0) {
        __threadfence();
        unsigned prev = atomicAdd(&g_done, 1u);
        s_last = (prev == gridDim.x - 1);
    }
    __syncthreads();
    if (s_last && wid == 0) {
        __threadfence();
        float s = 0.f;
        const float4* gp = (const float4*)g_partial;
#pragma unroll
        for (int k = 0; k < 4; k++) {
            float4 v = __ldcg(gp + lane + 32 * k);
            s += (v.x + v.y) + (v.z + v.w);
        }
#pragma unroll
        for (int o = 16; o > 0; o >>= 1)
            s += __shfl_down_sync(FULLMASK, s, o);
        if (lane == 0) {
            out[0] = s * (1.0f / (float)NB);
            g_done = 0;   // reset for next graph replay (deterministic)
        }
    }
}

extern "C" void kernel_launch(void* const* d_in, const int* in_sizes, int n_in,
                              void* d_out, int out_size) {
    const float* emissions = (const float*)d_in[0];
    const int*   tags      = (const int*)d_in[1];
    const int*   mask      = (const int*)d_in[2];
    const float* trans     = (const float*)d_in[3];
    const float* startt    = (const float*)d_in[4];
    const float* endt      = (const float*)d_in[5];
    (void)in_sizes; (void)n_in; (void)out_size;

    crf_forward<<<NB / PAIRS, THREADS>>>(emissions, tags, mask, trans, startt,
                                         endt, (float*)d_out);
}